// round 8
// baseline (speedup 1.0000x reference)
#include <cuda_runtime.h>

// Problem shape (fixed by setup_inputs): x: (B=4, S=4096, D=64) f32; out: (B,S) f32
#define S_LEN  4096
#define D_DIM  64
#define CH     8               // chunk size (norm elements per L1 entry)
#define NCH    (S_LEN / CH)    // 512 chunks per row
#define NB     128             // grid (co-resident: 128 <= 148 SMs)
#define NT     512             // threads per block
#define QPB    128             // queries per block (32 blocks per batch row)

// Device-global scratch (no allocation). All counters are MONOTONIC across
// graph replays (launches are serialized, each adds a fixed amount).
__device__ float    g_norms[4 * S_LEN];
__device__ unsigned g_ctr;          // ticket: +NB per launch -> generation id
__device__ unsigned g_seg[NB];      // per-segment completion: +1 per launch

__device__ __forceinline__ unsigned ld_acquire_gpu(const unsigned* p) {
    unsigned v;
    asm volatile("ld.acquire.gpu.global.u32 %0, [%1];" : "=r"(v) : "l"(p) : "memory");
    return v;
}
__device__ __forceinline__ void red_release_add(unsigned* p, unsigned v) {
    asm volatile("red.release.gpu.global.add.u32 [%0], %1;" :: "l"(p), "r"(v) : "memory");
}

// Max m in [0,7] s.t. windows [pos-k*s, pos-(k-1)*s) are all clean for k<=m.
// tab[c] = min over s chunks starting at c. The 7 loads are independent.
__device__ __forceinline__ int leading_clean7(const float* __restrict__ tab,
                                              int pos, int s, float thr) {
    bool ok = true;
    int m = 0;
#pragma unroll
    for (int k = 1; k <= 7; k++) {
        const int npos = pos - k * s;
        const float v = tab[npos >= 0 ? npos : 0];
        ok = ok && (npos >= 0) && (v >= thr);
        m += ok ? 1 : 0;
    }
    return m;
}

__device__ __forceinline__ float abs4(float4 v) {
    return fabsf(v.x) + fabsf(v.y) + fabsf(v.z) + fabsf(v.w);
}
__device__ __forceinline__ float min8(float4 a, float4 b) {
    return fminf(fminf(fminf(a.x, a.y), fminf(a.z, a.w)),
                 fminf(fminf(b.x, b.y), fminf(b.z, b.w)));
}

__global__ void __launch_bounds__(NT, 1) fused_kernel(const float* __restrict__ x,
                                                      float* __restrict__ out) {
    __shared__ float sn[S_LEN];      // 16 KB norms row
    __shared__ float sL1[NCH];       // min over 1 chunk  (8 elems)
    __shared__ float sL8[NCH];       // min over 8 chunks
    __shared__ float sL64[NCH];      // min over 64 chunks
    __shared__ unsigned sgen;

    const int tid = threadIdx.x;
    const int blk = blockIdx.x;

    // ---------- Phase 1: norms for this block's segment (128 rows) ----------
    // Block blk handles rows [blk*128, blk*128+128) = batch (blk>>5),
    // segment (blk&31). 4 threads per row, loads issued back-to-back (MLP=4).
    {
        const int gtid = blk * NT + tid;
        const int row  = gtid >> 2;
        const int q    = gtid & 3;
        const float4* src = reinterpret_cast<const float4*>(x + (size_t)row * D_DIM) + q * 4;
        const float4 a0 = src[0];
        const float4 a1 = src[1];
        const float4 a2 = src[2];
        const float4 a3 = src[3];

        if (tid == 0) sgen = atomicAdd(&g_ctr, 1u) / NB;   // generation (replay index)

        float s = (abs4(a0) + abs4(a1)) + (abs4(a2) + abs4(a3));
        s += __shfl_xor_sync(0xffffffffu, s, 1);
        s += __shfl_xor_sync(0xffffffffu, s, 2);
        if (q == 0) g_norms[row] = s;
    }
    __syncthreads();                      // CTA-scope HB: all STGs ordered before release
    if (tid == 0) red_release_add(&g_seg[blk], 1u);   // publish segment blk

    // ---------- Phase 2: per-thread acquire on the ONE segment it needs -----
    const int b      = blk >> 5;          // batch row
    const int tbase  = (blk & 31) * QPB;
    const unsigned target = sgen + 1u;    // flag value meaning "done this replay"

    {
        // Thread tid owns chunk tid (floats [8*tid, 8*tid+8)), which lives in
        // segment tid>>4 of batch b. Poll only that producer's flag.
        const unsigned* flag = &g_seg[b * 32 + (tid >> 4)];
        while (ld_acquire_gpu(flag) < target) { }

        const float4* srcN = reinterpret_cast<const float4*>(g_norms + (size_t)b * S_LEN);
        const float4 a0 = srcN[2 * tid + 0];
        const float4 a1 = srcN[2 * tid + 1];
        float4* dst = reinterpret_cast<float4*>(sn);
        dst[2 * tid + 0] = a0;
        dst[2 * tid + 1] = a1;
        sL1[tid] = min8(a0, a1);
    }
    __syncthreads();

    // L8[c] = min over L1[c .. c+7] (clamped tail reads are harmless).
    {
        float m = sL1[tid];
#pragma unroll
        for (int k = 1; k < 8; k++) {
            const int idx = tid + k;
            m = fminf(m, sL1[idx < NCH ? idx : NCH - 1]);
        }
        sL8[tid] = m;
    }
    __syncthreads();

    // L64[c] = min over 64 chunks = 8 L8 entries at stride 8.
    {
        float m = sL8[tid];
#pragma unroll
        for (int k = 1; k < 8; k++) {
            const int idx = tid + k * 8;
            m = fminf(m, sL8[idx < NCH ? idx : NCH - 1]);
        }
        sL64[tid] = m;
    }
    __syncthreads();

    // ---------- Phase 3: one query per thread (tid < QPB) ----------
    if (tid < QPB) {
        const int t = tbase + tid;
        const float thr = 0.7f * (sn[t] + 1e-8f);

        // A) partial chunk [cb, t): predicated scan, ascending keeps max j.
        const int cb = t & ~(CH - 1);
        int best = -1;
#pragma unroll
        for (int k = 0; k < CH - 1; k++) {
            const int j = cb + k;
            if (j < t && sn[j] < thr) best = j;
        }

        // B) 7-ary descend over scales {64, 8, 1}; C) scan dirty chunk pos-1.
        if (best < 0 && cb > 0) {
            int pos = cb >> 3;                       // in [1, 511]
            pos -= 64 * leading_clean7(sL64, pos, 64, thr);
            pos -= 8  * leading_clean7(sL8,  pos, 8,  thr);
            pos -=      leading_clean7(sL1,  pos, 1,  thr);
            if (pos > 0) {
                const int base = (pos - 1) * CH;     // guaranteed-dirty chunk
#pragma unroll
                for (int k = 0; k < CH; k++)
                    if (sn[base + k] < thr) best = base + k;
            }
        }

        out[(size_t)b * S_LEN + t] = best >= 0 ? (float)(t - best) : 0.0f;
    }
}

// ---------------------------------------------------------------------------
// Launch: single fused kernel, 128 blocks x 512 threads.
// ---------------------------------------------------------------------------
extern "C" void kernel_launch(void* const* d_in, const int* in_sizes, int n_in,
                              void* d_out, int out_size) {
    const float* x = (const float*)d_in[0];
    float* out = (float*)d_out;
    fused_kernel<<<NB, NT>>>(x, out);
}

// round 9
// speedup vs baseline: 1.3063x; 1.3063x over previous
#include <cuda_runtime.h>

// Problem shape (fixed by setup_inputs): x: (B=4, S=4096, D=64) f32; out: (B,S) f32
#define S_LEN  4096
#define D_DIM  64
#define CH     8               // chunk size (norm elements per L1 entry)
#define NCH    (S_LEN / CH)    // 512 chunks per row
#define NB     128             // grid (co-resident: 128 <= 148 SMs)
#define NT     512             // threads per block
#define QPB    128             // queries per block (32 blocks per batch row)

// Device-global scratch (no allocation). Counters are MONOTONIC across graph
// replays: each launch adds exactly 32 to each batch counter; the generation
// is recovered from the counter value itself (see s_target derivation).
__device__ float    g_norms[4 * S_LEN];
__device__ unsigned g_done[4 * 32];    // counter for batch b at [b*32] (128B apart)

__device__ __forceinline__ unsigned ld_acquire_gpu(const unsigned* p) {
    unsigned v;
    asm volatile("ld.acquire.gpu.global.u32 %0, [%1];" : "=r"(v) : "l"(p) : "memory");
    return v;
}
__device__ __forceinline__ unsigned ld_relaxed_gpu(const unsigned* p) {
    unsigned v;
    asm volatile("ld.relaxed.gpu.global.u32 %0, [%1];" : "=r"(v) : "l"(p) : "memory");
    return v;
}
__device__ __forceinline__ void red_release_add(unsigned* p, unsigned v) {
    asm volatile("red.release.gpu.global.add.u32 [%0], %1;" :: "l"(p), "r"(v) : "memory");
}

// Max m in [0,7] s.t. windows [pos-k*s, pos-(k-1)*s) are all clean for k<=m.
// tab[c] = min over s chunks starting at c. The 7 loads are independent.
__device__ __forceinline__ int leading_clean7(const float* __restrict__ tab,
                                              int pos, int s, float thr) {
    bool ok = true;
    int m = 0;
#pragma unroll
    for (int k = 1; k <= 7; k++) {
        const int npos = pos - k * s;
        const float v = tab[npos >= 0 ? npos : 0];
        ok = ok && (npos >= 0) && (v >= thr);
        m += ok ? 1 : 0;
    }
    return m;
}

__device__ __forceinline__ float abs4(float4 v) {
    return fabsf(v.x) + fabsf(v.y) + fabsf(v.z) + fabsf(v.w);
}
__device__ __forceinline__ float min8(float4 a, float4 b) {
    return fminf(fminf(fminf(a.x, a.y), fminf(a.z, a.w)),
                 fminf(fminf(b.x, b.y), fminf(b.z, b.w)));
}

__global__ void __launch_bounds__(NT, 1) fused_kernel(const float* __restrict__ x,
                                                      float* __restrict__ out) {
    __shared__ float sn[S_LEN];      // 16 KB norms row
    __shared__ float sL1[NCH];       // min over 1 chunk  (8 elems)
    __shared__ float sL8[NCH];       // min over 8 chunks
    __shared__ float sL64[NCH];      // min over 64 chunks
    __shared__ unsigned s_target;

    const int tid = threadIdx.x;
    const int blk = blockIdx.x;
    const int b   = blk >> 5;        // batch row owned by this block's segment

    // Derive this replay's completion target from the counter itself.
    // At launch the counter is exactly 32*gen (replays serialize); this block
    // has not released yet, so v0 in [32g, 32g+31] -> target = 32*(g+1).
    if (tid == 0) {
        const unsigned v0 = ld_relaxed_gpu(&g_done[b * 32]);
        s_target = ((v0 >> 5) + 1u) << 5;
    }

    // ---------- Phase 1: norms for this block's segment (128 rows) ----------
    // 4 threads per row; 4 independent float4 loads back-to-back (MLP=4);
    // warp covers 2KB contiguous (fully coalesced).
    {
        const int gtid = blk * NT + tid;
        const int row  = gtid >> 2;
        const int q    = gtid & 3;
        const float4* src = reinterpret_cast<const float4*>(x + (size_t)row * D_DIM) + q * 4;
        const float4 a0 = src[0];
        const float4 a1 = src[1];
        const float4 a2 = src[2];
        const float4 a3 = src[3];
        float s = (abs4(a0) + abs4(a1)) + (abs4(a2) + abs4(a3));
        s += __shfl_xor_sync(0xffffffffu, s, 1);
        s += __shfl_xor_sync(0xffffffffu, s, 2);
        if (q == 0) g_norms[row] = s;
    }
    __syncthreads();     // CTA-order all g_norms stores before the release
    if (tid == 0) {
        red_release_add(&g_done[b * 32], 1u);       // publish this segment
        // Single read-only poller per block: no RMW serialization, 32 pollers
        // per line max, each iteration ~1 L2 round-trip.
        while (ld_acquire_gpu(&g_done[b * 32]) < s_target) { }
    }
    __syncthreads();     // acquire made batch b's norms visible; fan out

    // ---------- Phase 2: stage row + build tables (1 chunk per thread) -----
    const int tbase = (blk & 31) * QPB;
    {
        const float4* srcN = reinterpret_cast<const float4*>(g_norms + (size_t)b * S_LEN);
        const float4 a0 = srcN[2 * tid + 0];        // chunk tid = floats [8t, 8t+8)
        const float4 a1 = srcN[2 * tid + 1];
        float4* dst = reinterpret_cast<float4*>(sn);
        dst[2 * tid + 0] = a0;
        dst[2 * tid + 1] = a1;
        sL1[tid] = min8(a0, a1);
    }
    __syncthreads();

    // L8[c] = min over L1[c .. c+7] (clamped tail reads are harmless).
    {
        float m = sL1[tid];
#pragma unroll
        for (int k = 1; k < 8; k++) {
            const int idx = tid + k;
            m = fminf(m, sL1[idx < NCH ? idx : NCH - 1]);
        }
        sL8[tid] = m;
    }
    __syncthreads();

    // L64[c] = min over 64 chunks = 8 L8 entries at stride 8.
    {
        float m = sL8[tid];
#pragma unroll
        for (int k = 1; k < 8; k++) {
            const int idx = tid + k * 8;
            m = fminf(m, sL8[idx < NCH ? idx : NCH - 1]);
        }
        sL64[tid] = m;
    }
    __syncthreads();

    // ---------- Phase 3: one query per thread (tid < QPB) ----------
    if (tid < QPB) {
        const int t = tbase + tid;
        const float thr = 0.7f * (sn[t] + 1e-8f);

        // A) partial chunk [cb, t): predicated scan, ascending keeps max j.
        const int cb = t & ~(CH - 1);
        int best = -1;
#pragma unroll
        for (int k = 0; k < CH - 1; k++) {
            const int j = cb + k;
            if (j < t && sn[j] < thr) best = j;
        }

        // B) 7-ary descend over scales {64, 8, 1}; C) scan dirty chunk pos-1.
        if (best < 0 && cb > 0) {
            int pos = cb >> 3;                       // in [1, 511]
            pos -= 64 * leading_clean7(sL64, pos, 64, thr);
            pos -= 8  * leading_clean7(sL8,  pos, 8,  thr);
            pos -=      leading_clean7(sL1,  pos, 1,  thr);
            if (pos > 0) {
                const int base = (pos - 1) * CH;     // guaranteed-dirty chunk
#pragma unroll
                for (int k = 0; k < CH; k++)
                    if (sn[base + k] < thr) best = base + k;
            }
        }

        out[(size_t)b * S_LEN + t] = best >= 0 ? (float)(t - best) : 0.0f;
    }
}

// ---------------------------------------------------------------------------
// Launch: single fused kernel, 128 blocks x 512 threads.
// ---------------------------------------------------------------------------
extern "C" void kernel_launch(void* const* d_in, const int* in_sizes, int n_in,
                              void* d_out, int out_size) {
    const float* x = (const float*)d_in[0];
    float* out = (float*)d_out;
    fused_kernel<<<NB, NT>>>(x, out);
}